// round 11
// baseline (speedup 1.0000x reference)
#include <cuda_runtime.h>

#define BSEQ 512
#define LSEQ 512
#define AA   20
#define CCH  8
#define NREST 8
#define XPAD 21              // x_sh row pitch: gcd(21,32)=1 -> conflict-free

// Precomputed: effective conv map (transposed, [c][p]) and U = I + V
__device__ float g_W[CCH][LSEQ];
__device__ float g_U[AA * AA];

// ---------------------------------------------------------------------------
// Precompute kernel (primary): triggers PDL completion at entry so the main
// kernel can begin staging x immediately. Blocks 0..7 -> one W_eff channel
// via the adjoint of the conv+pool pipeline; block 8 -> U; 9..168 -> zero out.
// ---------------------------------------------------------------------------
template<int LEN2>
__device__ __forceinline__ void adj_layer(const float (*cur)[256],
                                          float (*nxt)[256],
                                          const float* __restrict__ w) {
    for (int idx = threadIdx.x; idx < CCH * LEN2; idx += 256) {
        const int i = idx / LEN2;
        const int p = idx % LEN2;
        float acc = 0.f;
        #pragma unroll
        for (int o = 0; o < CCH; ++o) {
            #pragma unroll
            for (int k = 0; k < 3; ++k) {
                const int q = p - k + 1;
                if (q >= 0 && q < LEN2)
                    acc += w[(o * CCH + i) * 3 + k] * 0.5f * cur[o][q >> 1];
            }
        }
        nxt[i][p] = acc;
    }
    __syncthreads();
}

__global__ void __launch_bounds__(256)
precompute_kernel(const float* __restrict__ lpm,
                  const float* __restrict__ pm,
                  const float* __restrict__ w_first,
                  const float* __restrict__ w_rest,
                  float* __restrict__ out) {
#if __CUDA_ARCH__ >= 900
    cudaTriggerProgrammaticLaunchCompletion();
#endif
    const int blk = blockIdx.x;
    const int tid = threadIdx.x;

    if (blk < CCH) {
        __shared__ float bufA[CCH][256];
        __shared__ float bufB[CCH][256];
        __shared__ float wsh[NREST * CCH * CCH * 3];

        for (int i = tid; i < NREST * CCH * CCH * 3; i += 256)
            wsh[i] = w_rest[i];
        if (tid < CCH) bufA[tid][0] = (tid == blk) ? 1.f : 0.f;
        __syncthreads();

        float (*cur)[256] = bufA;
        float (*nxt)[256] = bufB;
        float (*tmp)[256];
        #define STEP(L2, LI) \
            adj_layer<L2>(cur, nxt, wsh + (LI) * 192); \
            tmp = cur; cur = nxt; nxt = tmp;
        STEP(2, 7)  STEP(4, 6)  STEP(8, 5)   STEP(16, 4)
        STEP(32, 3) STEP(64, 2) STEP(128, 1) STEP(256, 0)
        #undef STEP

        for (int p = tid; p < LSEQ; p += 256) {
            float acc = 0.f;
            #pragma unroll
            for (int o = 0; o < CCH; ++o) {
                #pragma unroll
                for (int k = 0; k < 3; ++k) {
                    const int q = p - k + 1;
                    if (q >= 0 && q < LSEQ)
                        acc += w_first[o * 3 + k] * 0.5f * cur[o][q >> 1];
                }
            }
            g_W[blk][p] = acc;            // transposed layout [c][p]
        }
    } else if (blk == CCH) {
        // U[a][i] = delta(a,i) + V[a][i]
        for (int idx = tid; idx < AA * AA; idx += 256) {
            const int a = idx / AA, i = idx % AA;
            float v = (a == i) ? 1.f : 0.f;
            if (i != a && i != AA - 1) {
                const int r = (a < i) ? a : i;
                const int c = (a < i) ? i : a;
                float l = lpm[r * AA + c];
                l = fminf(fmaxf(l, 1e-3f), 1.f);
                v = l * pm[r * AA + c];
            }
            g_U[idx] = v;
        }
    } else {
        const int z = blk - (CCH + 1);          // 0..159
        if (tid < 128)
            reinterpret_cast<float4*>(out)[z * 128 + tid] =
                make_float4(0.f, 0.f, 0.f, 0.f);
    }
}

// ---------------------------------------------------------------------------
// Main kernel (secondary, PDL): grid 1024 = 512 sequences x 2 halves.
// Stage x FIRST (independent of primary), grid-dependency-sync, stage W,
// then the R4 scalar GEMM (32 regs -> 7 blocks/SM, single wave) + value-
// combining reduce + U epilogue with atomics.
// ---------------------------------------------------------------------------
__global__ void __launch_bounds__(256, 7)
main_kernel(const float* __restrict__ x, float* __restrict__ out) {
    __shared__ float x_sh[256 * XPAD];      // 21504 B
    __shared__ float W_sh[CCH * 256];       //  8192 B
    __shared__ float g_sh[AA][CCH];

    const int bi   = blockIdx.x;
    const int b    = bi >> 1;
    const int half = bi & 1;
    const int tid  = threadIdx.x;
    const int s    = tid & 31;
    const int w    = tid >> 5;
    const int gq   = w >> 1;                // a-group 0..3 (rows 5gq..5gq+4)
    const int h    = w & 1;                 // c-half 0..1 (cols 4h..4h+3)

    // Stage x half-chunk FIRST (overlaps the still-running precompute).
    {
        const float4* xg = reinterpret_cast<const float4*>(x)
                         + (size_t)b * 2560 + half * 1280;
        #pragma unroll
        for (int it = 0; it < 5; ++it) {
            const int i = tid + it * 256;    // < 1280
            const float4 v = xg[i];
            const int p  = i / 5;
            const int a0 = (i - p * 5) * 4;
            float* d = &x_sh[p * XPAD + a0];
            d[0] = v.x; d[1] = v.y; d[2] = v.z; d[3] = v.w;
        }
    }

    // Wait for primary grid completion (g_W, g_U, zeroed out all visible).
#if __CUDA_ARCH__ >= 900
    cudaGridDependencySynchronize();
#endif

    // Stage W chunk [8][256].
    {
        const float4* Wg = reinterpret_cast<const float4*>(g_W);
        #pragma unroll
        for (int it = 0; it < 2; ++it) {
            const int i = tid + it * 256;    // < 512
            const int c = i >> 6, p4 = i & 63;
            reinterpret_cast<float4*>(W_sh)[c * 64 + p4] =
                Wg[c * 128 + half * 64 + p4];
        }
    }
    __syncthreads();

    // R4 scalar GEMM: conflict-free LDS.32 on both operands, immediates only.
    float acc[5][4];
    #pragma unroll
    for (int m = 0; m < 5; ++m)
        #pragma unroll
        for (int n = 0; n < 4; ++n) acc[m][n] = 0.f;

    const float* xp = &x_sh[s * XPAD + gq * 5];
    const float* wp = &W_sh[(h * 4) * 256 + s];
    #pragma unroll
    for (int j = 0; j < 8; ++j) {            // p = 32*j + s
        float xr[5], wr[4];
        #pragma unroll
        for (int m = 0; m < 5; ++m) xr[m] = xp[j * 32 * XPAD + m];
        #pragma unroll
        for (int n = 0; n < 4; ++n) wr[n] = wp[n * 256 + j * 32];
        #pragma unroll
        for (int m = 0; m < 5; ++m)
            #pragma unroll
            for (int n = 0; n < 4; ++n)
                acc[m][n] += xr[m] * wr[n];
    }

    // Value-combining butterfly reduce over lanes.
    const bool hi16 = (s & 16) != 0;
    const bool hi8  = (s & 8) != 0;
    float r1[5][2];
    #pragma unroll
    for (int m = 0; m < 5; ++m) {
        #pragma unroll
        for (int u = 0; u < 2; ++u) {
            const float a  = acc[m][2 * u];
            const float bb = acc[m][2 * u + 1];
            const float keep = hi16 ? bb : a;
            const float send = hi16 ? a : bb;
            r1[m][u] = keep + __shfl_xor_sync(0xffffffffu, send, 16);
        }
    }
    float r2[5];
    #pragma unroll
    for (int m = 0; m < 5; ++m) {
        const float a  = r1[m][0];
        const float bb = r1[m][1];
        const float keep = hi8 ? bb : a;
        const float send = hi8 ? a : bb;
        r2[m] = keep + __shfl_xor_sync(0xffffffffu, send, 8);
    }
    #pragma unroll
    for (int m = 0; m < 5; ++m) {
        r2[m] += __shfl_xor_sync(0xffffffffu, r2[m], 4);
        r2[m] += __shfl_xor_sync(0xffffffffu, r2[m], 2);
        r2[m] += __shfl_xor_sync(0xffffffffu, r2[m], 1);
    }
    if ((s & 7) == 0) {
        const int n = 2 * ((s >> 3) & 1) + ((s >> 4) & 1);
        #pragma unroll
        for (int m = 0; m < 5; ++m)
            g_sh[gq * 5 + m][h * 4 + n] = r2[m];
    }
    __syncthreads();

    // out[b,i,c] += sum_a U[a][i] * g[a][c]   (2 halves combine via atomics)
    if (tid < AA * CCH) {
        const int i = tid >> 3;
        const int c = tid & 7;
        float r = 0.f;
        #pragma unroll
        for (int a = 0; a < AA; ++a)
            r += __ldg(&g_U[a * AA + i]) * g_sh[a][c];
        atomicAdd(&out[(size_t)b * (AA * CCH) + tid], r);
    }
}

// ---------------------------------------------------------------------------
extern "C" void kernel_launch(void* const* d_in, const int* in_sizes, int n_in,
                              void* d_out, int out_size) {
    const float* x       = (const float*)d_in[0];
    const float* lpm     = (const float*)d_in[2];
    const float* pm      = (const float*)d_in[3];
    const float* w_first = (const float*)d_in[4];
    const float* w_rest  = (const float*)d_in[5];
    float* out = (float*)d_out;

    // Primary: precompute W_eff / U and zero `out`.
    precompute_kernel<<<CCH + 1 + 160, 256>>>(lpm, pm, w_first, w_rest, out);

    // Secondary: PDL launch — begins (stage x) while primary still runs;
    // cudaGridDependencySynchronize() inside orders the g_W/g_U/out reads.
    cudaLaunchConfig_t cfg = {};
    cfg.gridDim  = dim3(BSEQ * 2, 1, 1);
    cfg.blockDim = dim3(256, 1, 1);
    cfg.dynamicSmemBytes = 0;
    cfg.stream = 0;
    cudaLaunchAttribute attrs[1];
    attrs[0].id = cudaLaunchAttributeProgrammaticStreamSerialization;
    attrs[0].val.programmaticStreamSerializationAllowed = 1;
    cfg.attrs = attrs;
    cfg.numAttrs = 1;
    cudaLaunchKernelEx(&cfg, main_kernel, x, (float*)d_out);
}

// round 12
// speedup vs baseline: 1.0572x; 1.0572x over previous
#include <cuda_runtime.h>
#include <cuda_bf16.h>

#define BSEQ 512
#define LSEQ 512
#define AA   20
#define CCH  8
#define NREST 8
#define PA   24      // xTp pitch (bf16): 48B rows -> conflict-free ldmatrix.trans
#define PW   264     // W smem pitch (bf16): 528B rows -> conflict-free ldmatrix

#define LDSM_X4_T(R, addr) \
    asm volatile("ldmatrix.sync.aligned.m8n8.x4.trans.shared.b16 " \
                 "{%0,%1,%2,%3}, [%4];" \
                 : "=r"((R)[0]), "=r"((R)[1]), "=r"((R)[2]), "=r"((R)[3]) \
                 : "r"(addr))
#define LDSM_X2(R, addr) \
    asm volatile("ldmatrix.sync.aligned.m8n8.x2.shared.b16 {%0,%1}, [%2];" \
                 : "=r"((R)[0]), "=r"((R)[1]) : "r"(addr))
#define MMA_BF16(C, A, B) \
    asm volatile("mma.sync.aligned.m16n8k16.row.col.f32.bf16.bf16.f32 " \
                 "{%0,%1,%2,%3}, {%4,%5,%6,%7}, {%8,%9}, {%0,%1,%2,%3};" \
                 : "+f"((C)[0]), "+f"((C)[1]), "+f"((C)[2]), "+f"((C)[3]) \
                 : "r"((A)[0]), "r"((A)[1]), "r"((A)[2]), "r"((A)[3]), \
                   "r"((B)[0]), "r"((B)[1]))

// Precomputed: W_eff split into bf16 hi/lo pairs, and U = I + V.
__device__ __nv_bfloat16 g_Whi[CCH][LSEQ];
__device__ __nv_bfloat16 g_Wlo[CCH][LSEQ];
__device__ float g_U[AA * AA];

// ---------------------------------------------------------------------------
// Precompute kernel (primary, PDL trigger at entry). Blocks 0..7 -> one W_eff
// channel via the conv+pool adjoint, emitted as bf16 hi/lo; block 8 -> U;
// blocks 9..168 -> zero out.
// ---------------------------------------------------------------------------
template<int LEN2>
__device__ __forceinline__ void adj_layer(const float (*cur)[256],
                                          float (*nxt)[256],
                                          const float* __restrict__ w) {
    for (int idx = threadIdx.x; idx < CCH * LEN2; idx += 256) {
        const int i = idx / LEN2;
        const int p = idx % LEN2;
        float acc = 0.f;
        #pragma unroll
        for (int o = 0; o < CCH; ++o) {
            #pragma unroll
            for (int k = 0; k < 3; ++k) {
                const int q = p - k + 1;
                if (q >= 0 && q < LEN2)
                    acc += w[(o * CCH + i) * 3 + k] * 0.5f * cur[o][q >> 1];
            }
        }
        nxt[i][p] = acc;
    }
    __syncthreads();
}

__global__ void __launch_bounds__(256)
precompute_kernel(const float* __restrict__ lpm,
                  const float* __restrict__ pm,
                  const float* __restrict__ w_first,
                  const float* __restrict__ w_rest,
                  float* __restrict__ out) {
#if __CUDA_ARCH__ >= 900
    cudaTriggerProgrammaticLaunchCompletion();
#endif
    const int blk = blockIdx.x;
    const int tid = threadIdx.x;

    if (blk < CCH) {
        __shared__ float bufA[CCH][256];
        __shared__ float bufB[CCH][256];
        __shared__ float wsh[NREST * CCH * CCH * 3];

        for (int i = tid; i < NREST * CCH * CCH * 3; i += 256)
            wsh[i] = w_rest[i];
        if (tid < CCH) bufA[tid][0] = (tid == blk) ? 1.f : 0.f;
        __syncthreads();

        float (*cur)[256] = bufA;
        float (*nxt)[256] = bufB;
        float (*tmp)[256];
        #define STEP(L2, LI) \
            adj_layer<L2>(cur, nxt, wsh + (LI) * 192); \
            tmp = cur; cur = nxt; nxt = tmp;
        STEP(2, 7)  STEP(4, 6)  STEP(8, 5)   STEP(16, 4)
        STEP(32, 3) STEP(64, 2) STEP(128, 1) STEP(256, 0)
        #undef STEP

        for (int p = tid; p < LSEQ; p += 256) {
            float acc = 0.f;
            #pragma unroll
            for (int o = 0; o < CCH; ++o) {
                #pragma unroll
                for (int k = 0; k < 3; ++k) {
                    const int q = p - k + 1;
                    if (q >= 0 && q < LSEQ)
                        acc += w_first[o * 3 + k] * 0.5f * cur[o][q >> 1];
                }
            }
            const __nv_bfloat16 hi = __float2bfloat16(acc);
            g_Whi[blk][p] = hi;
            g_Wlo[blk][p] = __float2bfloat16(acc - __bfloat162float(hi));
        }
    } else if (blk == CCH) {
        // U[a][i] = delta(a,i) + V[a][i]
        for (int idx = tid; idx < AA * AA; idx += 256) {
            const int a = idx / AA, i = idx % AA;
            float v = (a == i) ? 1.f : 0.f;
            if (i != a && i != AA - 1) {
                const int r = (a < i) ? a : i;
                const int c = (a < i) ? i : a;
                float l = lpm[r * AA + c];
                l = fminf(fmaxf(l, 1e-3f), 1.f);
                v = l * pm[r * AA + c];
            }
            g_U[idx] = v;
        }
    } else {
        const int z = blk - (CCH + 1);          // 0..159
        if (tid < 128)
            reinterpret_cast<float4*>(out)[z * 128 + tid] =
                make_float4(0.f, 0.f, 0.f, 0.f);
    }
}

// ---------------------------------------------------------------------------
// Main kernel (secondary, PDL): grid 1024 = 512 sequences x 2 halves of 256
// positions. x staged as bf16 [p][a] (exact for one-hot); GEMM on tensor
// cores: per warp a K=32 slice, 2 M-tiles, W split hi+lo into the same fp32
// accumulator. Cross-warp reduce in smem, U epilogue, atomicAdd per half.
// ---------------------------------------------------------------------------
__global__ void __launch_bounds__(256, 5)
main_kernel(const float* __restrict__ x, float* __restrict__ out) {
    __shared__ __nv_bfloat16 xTp[256 * PA + 32];   // 12352 B (+slack for ldsm)
    __shared__ __nv_bfloat16 Whi_sh[CCH * PW];     //  4224 B
    __shared__ __nv_bfloat16 Wlo_sh[CCH * PW];     //  4224 B
    __shared__ float Dp[8][32][8];                 //  8192 B
    __shared__ float g_sh[AA][CCH];

    const int bi   = blockIdx.x;
    const int b    = bi >> 1;
    const int half = bi & 1;
    const int tid  = threadIdx.x;
    const int lane = tid & 31;
    const int w    = tid >> 5;

    // ---- Stage x FIRST (overlaps the still-running precompute) ------------
    // Coalesced float4 loads; bf16 convert (exact for 0/1); store [p][a].
    {
        const float4* xg = reinterpret_cast<const float4*>(x)
                         + (size_t)b * 2560 + half * 1280;
        #pragma unroll
        for (int it = 0; it < 5; ++it) {
            const int i = tid + it * 256;    // < 1280
            const float4 v = xg[i];
            const int p  = i / 5;
            const int a0 = (i - p * 5) * 4;
            __nv_bfloat162 u0 = __floats2bfloat162_rn(v.x, v.y);
            __nv_bfloat162 u1 = __floats2bfloat162_rn(v.z, v.w);
            uint2 pk;
            pk.x = *reinterpret_cast<unsigned*>(&u0);
            pk.y = *reinterpret_cast<unsigned*>(&u1);
            *reinterpret_cast<uint2*>(&xTp[p * PA + a0]) = pk;
        }
    }

#if __CUDA_ARCH__ >= 900
    cudaGridDependencySynchronize();
#endif

    // ---- Stage W hi/lo: 8 rows x 32 uint4 per array (exactly 256 threads) --
    {
        const uint4* Hg = reinterpret_cast<const uint4*>(g_Whi);
        const uint4* Lg = reinterpret_cast<const uint4*>(g_Wlo);
        const int c = tid >> 5, q = tid & 31;
        const uint4 vh = Hg[c * 64 + half * 32 + q];
        const uint4 vl = Lg[c * 64 + half * 32 + q];
        *reinterpret_cast<uint4*>(&Whi_sh[c * PW + q * 8]) = vh;
        *reinterpret_cast<uint4*>(&Wlo_sh[c * PW + q * 8]) = vl;
    }
    __syncthreads();

    // ---- Tensor-core GEMM: warp w owns K slice [32w, 32w+32) ---------------
    const int kbase = w * 32;
    const int r8 = lane & 7;
    const int g4 = lane >> 3;
    const unsigned xb = (unsigned)__cvta_generic_to_shared(xTp);
    const unsigned hb = (unsigned)__cvta_generic_to_shared(Whi_sh);
    const unsigned lb = (unsigned)__cvta_generic_to_shared(Wlo_sh);

    float C0[4] = {0.f, 0.f, 0.f, 0.f};
    float C1[4] = {0.f, 0.f, 0.f, 0.f};

    // A (trans): tile g: stored row p = k + 8*(g>=2) + r8, col-bytes 16*(g&1).
    const unsigned aoff = (unsigned)((g4 & 1) << 4);
    // B: lanes 0-7 -> k+0, lanes 8-15 -> k+8; row c = lane&7.
    const unsigned bco = (unsigned)((lane & 7) * (PW * 2) + ((g4 & 1) << 4));

    #pragma unroll
    for (int kk = 0; kk < 32; kk += 16) {
        const int k = kbase + kk;
        const unsigned arow =
            xb + (unsigned)((k + ((g4 >> 1) << 3) + r8) * (PA * 2)) + aoff;
        unsigned A0[4], A1[4];
        LDSM_X4_T(A0, arow);           // M-tile 0: a cols 0-15
        LDSM_X4_T(A1, arow + 32u);     // M-tile 1: a cols 16-31 (20-31 pad)
        const unsigned bb = (unsigned)(k * 2) + bco;
        unsigned Bh[2], Bl[2];
        LDSM_X2(Bh, hb + bb);
        LDSM_X2(Bl, lb + bb);
        MMA_BF16(C0, A0, Bh);
        MMA_BF16(C0, A0, Bl);          // W = hi + lo, same accumulator
        MMA_BF16(C1, A1, Bh);
        MMA_BF16(C1, A1, Bl);
    }

    // ---- Park per-warp partials; deterministic 8-way cross-warp reduce -----
    {
        const int q2 = (lane & 3) * 2, tr = lane >> 2;
        *reinterpret_cast<float2*>(&Dp[w][tr     ][q2]) = make_float2(C0[0], C0[1]);
        *reinterpret_cast<float2*>(&Dp[w][tr +  8][q2]) = make_float2(C0[2], C0[3]);
        *reinterpret_cast<float2*>(&Dp[w][tr + 16][q2]) = make_float2(C1[0], C1[1]);
        *reinterpret_cast<float2*>(&Dp[w][tr + 24][q2]) = make_float2(C1[2], C1[3]);
    }
    __syncthreads();

    if (tid < AA * CCH) {
        const int a = tid >> 3, c = tid & 7;
        float sum = 0.f;
        #pragma unroll
        for (int ww = 0; ww < 8; ++ww) sum += Dp[ww][a][c];
        g_sh[a][c] = sum;
    }
    __syncthreads();

    // out[b,i,c] += sum_a U[a][i] * g[a][c]   (2 halves combine via atomics)
    if (tid < AA * CCH) {
        const int i = tid >> 3;
        const int c = tid & 7;
        float r = 0.f;
        #pragma unroll
        for (int a = 0; a < AA; ++a)
            r += __ldg(&g_U[a * AA + i]) * g_sh[a][c];
        atomicAdd(&out[(size_t)b * (AA * CCH) + tid], r);
    }
}

// ---------------------------------------------------------------------------
extern "C" void kernel_launch(void* const* d_in, const int* in_sizes, int n_in,
                              void* d_out, int out_size) {
    const float* x       = (const float*)d_in[0];
    const float* lpm     = (const float*)d_in[2];
    const float* pm      = (const float*)d_in[3];
    const float* w_first = (const float*)d_in[4];
    const float* w_rest  = (const float*)d_in[5];
    float* out = (float*)d_out;

    // Primary: precompute W hi/lo + U, zero out; triggers PDL at entry.
    precompute_kernel<<<CCH + 1 + 160, 256>>>(lpm, pm, w_first, w_rest, out);

    // Secondary: PDL launch — begins (stage x) while primary still runs.
    cudaLaunchConfig_t cfg = {};
    cfg.gridDim  = dim3(BSEQ * 2, 1, 1);
    cfg.blockDim = dim3(256, 1, 1);
    cfg.dynamicSmemBytes = 0;
    cfg.stream = 0;
    cudaLaunchAttribute attrs[1];
    attrs[0].id = cudaLaunchAttributeProgrammaticStreamSerialization;
    attrs[0].val.programmaticStreamSerializationAllowed = 1;
    cfg.attrs = attrs;
    cfg.numAttrs = 1;
    cudaLaunchKernelEx(&cfg, main_kernel, x, (float*)d_out);
}